// round 9
// baseline (speedup 1.0000x reference)
#include <cuda_runtime.h>

#define NN 100000
#define EE 1600000

// Scratch (allocation-free rule: __device__ globals)
__device__ float g_kw  [NN * 128];  // interleaved: [n][0:64]=k row, [n][64:128]=hw row
__device__ float g_q   [NN * 64];
__device__ int   g_cnt [NN];
__device__ int   g_roff[NN + 1];
__device__ int   g_cur [NN];
__device__ int   g_state[512];      // decoupled-lookback block state
__device__ int   g_esrc[EE];

// ---- tf32 helpers ----------------------------------------------------------
__device__ __forceinline__ unsigned to_tf32(float x)
{
    unsigned r; asm("cvt.rna.tf32.f32 %0, %1;" : "=r"(r) : "f"(x)); return r;
}
__device__ __forceinline__ void mma_tf32(float4& d, const unsigned* a, const unsigned* b)
{
    asm volatile(
        "mma.sync.aligned.m16n8k8.row.col.f32.tf32.tf32.f32 "
        "{%0,%1,%2,%3}, {%4,%5,%6,%7}, {%8,%9}, {%0,%1,%2,%3};"
        : "+f"(d.x), "+f"(d.y), "+f"(d.z), "+f"(d.w)
        : "r"(a[0]), "r"(a[1]), "r"(a[2]), "r"(a[3]), "r"(b[0]), "r"(b[1]));
}

// ---------------------------------------------------------------------------
// k = h@Wk, q = h@Wq, hw = h@W via 3xTF32 tensor-core MMA (fp32-class
// accuracy), PLUS the dst-histogram (RED ops hide under tensor work).
// 192 threads = 6 warps = 3 matrices x 2 m-halves. (R5/R8-proven.)
// ---------------------------------------------------------------------------
__global__ __launch_bounds__(192) void gemm_mma_hist_kernel(
    const float* __restrict__ h,
    const float* __restrict__ Wk,
    const float* __restrict__ Wq,
    const float* __restrict__ Ww,
    const int*   __restrict__ dst,
    int N, int E)
{
    __shared__ float sA[32 * 72];        // sA[node][kdim]
    __shared__ float sW[3 * 64 * 72];    // sW[sel][kdim][col]

    const int tid = threadIdx.x;

    // --- histogram slice (fire-and-forget L2 reductions) ---
    {
        const int eslice = (E + gridDim.x - 1) / gridDim.x;
        const int e0 = blockIdx.x * eslice;
        const int e1 = (e0 + eslice < E) ? e0 + eslice : E;
        for (int i = e0 + tid; i < e1; i += 192)
            atomicAdd(&g_cnt[dst[i]], 1);
    }

    for (int idx = tid; idx < 64 * 64; idx += 192) {
        const int i = idx >> 6, c = idx & 63;
        sW[0 * 64 * 72 + i * 72 + c] = Wk[idx];
        sW[1 * 64 * 72 + i * 72 + c] = Wq[idx];
        sW[2 * 64 * 72 + i * 72 + c] = Ww[idx];
    }
    const int base = blockIdx.x * 32;
    for (int idx = tid; idx < 32 * 64; idx += 192) {
        const int n = idx >> 6, c = idx & 63;
        const int gn = base + n;
        sA[n * 72 + c] = (gn < N) ? h[(size_t)gn * 64 + c] : 0.f;
    }
    __syncthreads();

    const int wid  = tid >> 5;
    const int lane = tid & 31;
    const int sel  = wid >> 1;          // 0:Wk 1:Wq 2:Ww
    const int mh   = wid & 1;           // m-half (16 nodes)
    const int g    = lane >> 2;         // 0..7
    const int t4   = lane & 3;          // 0..3

    float4 acc[8];
#pragma unroll
    for (int nt = 0; nt < 8; nt++) acc[nt] = make_float4(0.f, 0.f, 0.f, 0.f);

    const float* wm = sW + sel * 64 * 72;

#pragma unroll
    for (int ks = 0; ks < 8; ks++) {
        const int r0 = (mh * 16 + g) * 72 + ks * 8 + t4;
        const int r1 = (mh * 16 + g + 8) * 72 + ks * 8 + t4;
        const float a0f = sA[r0],     a1f = sA[r1];
        const float a2f = sA[r0 + 4], a3f = sA[r1 + 4];

        unsigned ahi[4], alo[4];
        ahi[0] = to_tf32(a0f); alo[0] = to_tf32(a0f - __uint_as_float(ahi[0]));
        ahi[1] = to_tf32(a1f); alo[1] = to_tf32(a1f - __uint_as_float(ahi[1]));
        ahi[2] = to_tf32(a2f); alo[2] = to_tf32(a2f - __uint_as_float(ahi[2]));
        ahi[3] = to_tf32(a3f); alo[3] = to_tf32(a3f - __uint_as_float(ahi[3]));

#pragma unroll
        for (int nt = 0; nt < 8; nt++) {
            const float b0f = wm[(ks * 8 + t4) * 72 + nt * 8 + g];
            const float b1f = wm[(ks * 8 + t4 + 4) * 72 + nt * 8 + g];
            unsigned bhi[2], blo[2];
            bhi[0] = to_tf32(b0f); blo[0] = to_tf32(b0f - __uint_as_float(bhi[0]));
            bhi[1] = to_tf32(b1f); blo[1] = to_tf32(b1f - __uint_as_float(bhi[1]));

            mma_tf32(acc[nt], ahi, bhi);
            mma_tf32(acc[nt], ahi, blo);
            mma_tf32(acc[nt], alo, bhi);
        }
    }

    const int gn0 = base + mh * 16 + g;
    const int gn1 = gn0 + 8;
#pragma unroll
    for (int nt = 0; nt < 8; nt++) {
        const int col = nt * 8 + t4 * 2;
        if (sel == 0) {
            if (gn0 < N) *(float2*)&g_kw[(size_t)gn0 * 128 + col] = make_float2(acc[nt].x, acc[nt].y);
            if (gn1 < N) *(float2*)&g_kw[(size_t)gn1 * 128 + col] = make_float2(acc[nt].z, acc[nt].w);
        } else if (sel == 1) {
            if (gn0 < N) *(float2*)&g_q[(size_t)gn0 * 64 + col] = make_float2(acc[nt].x, acc[nt].y);
            if (gn1 < N) *(float2*)&g_q[(size_t)gn1 * 64 + col] = make_float2(acc[nt].z, acc[nt].w);
        } else {
            if (gn0 < N) *(float2*)&g_kw[(size_t)gn0 * 128 + 64 + col] = make_float2(acc[nt].x, acc[nt].y);
            if (gn1 < N) *(float2*)&g_kw[(size_t)gn1 * 128 + 64 + col] = make_float2(acc[nt].z, acc[nt].w);
        }
    }
}

// ---------------------------------------------------------------------------
// Single-pass decoupled-lookback exclusive scan (runs alone on the stream).
// ---------------------------------------------------------------------------
__global__ __launch_bounds__(256) void scan_lb_kernel(int N, int E)
{
    __shared__ int wsum[8];
    __shared__ int sagg;
    __shared__ int sexc;
    const int t = threadIdx.x, lane = t & 31, wd = t >> 5;
    const int bid = blockIdx.x;
    const int i = bid * 256 + t;
    const int v = (i < N) ? g_cnt[i] : 0;

    int x = v;
#pragma unroll
    for (int off = 1; off < 32; off <<= 1) {
        int y = __shfl_up_sync(0xffffffffu, x, off);
        if (lane >= off) x += y;
    }
    if (lane == 31) wsum[wd] = x;
    __syncthreads();
    if (t < 8) {
        int w = wsum[t];
        int xs = w;
#pragma unroll
        for (int off = 1; off < 8; off <<= 1) {
            int y = __shfl_up_sync(0x000000ffu, xs, off);
            if (t >= off) xs += y;
        }
        wsum[t] = xs - w;
        if (t == 7) {
            sagg = xs;
            atomicExch(&g_state[bid], (xs << 2) | 1);
        }
    }
    __syncthreads();

    if (t == 0) {
        int exc = 0;
        if (bid > 0) {
            int j = bid - 1;
            while (true) {
                int s = atomicAdd(&g_state[j], 0);
                if ((s & 3) == 0) continue;
                exc += (s >> 2);
                if ((s & 3) == 2) break;
                j--;
            }
        }
        atomicExch(&g_state[bid], ((exc + sagg) << 2) | 2);
        sexc = exc;
    }
    __syncthreads();

    const int r = sexc + wsum[wd] + x - v;
    if (i < N) { g_roff[i] = r; g_cur[i] = r; }
    if (bid == 0 && t == 0) g_roff[N] = E;
}

__global__ void scatter_kernel(const int* __restrict__ src,
                               const int* __restrict__ dst, int E)
{
    int i = blockIdx.x * blockDim.x + threadIdx.x;
    if (i < E) {
        int p = atomicAdd(&g_cur[dst[i]], 1);
        g_esrc[p] = src[i];
    }
}

// ---------------------------------------------------------------------------
// Fused edge-softmax + aggregation, cp.async smem-ring pipelined.
// One warp per destination node. Ring: 16 slots x 512B per warp; 2 chunks of
// 8 edges in flight. esrc for a 32-edge window fetched in ONE LDG and
// distributed by shuffle. Consumption is smem-only: lane l owns elements
// [2l,2l+1]; head = l>>3; dot reduce = 3 xor shuffles (8-lane group); head
// weights for heads hh^1..hh^3 via 3 relative xor shuffles; z for other heads
// recovered AFTER the loop by 3 shuffles of z_own.
// ---------------------------------------------------------------------------
#define RING 16
#define CH   8

__global__ __launch_bounds__(128) void gather_kernel(
    const float* __restrict__ b,
    float* __restrict__ out,
    int N)
{
    extern __shared__ float ring[];   // [4 warps][RING][128]
    const int wslot = threadIdx.x >> 5;
    float* myring = ring + (size_t)wslot * (RING * 128);

    const int n    = (blockIdx.x * 128 + threadIdx.x) >> 5;
    const int lane = threadIdx.x & 31;
    if (n >= N) return;

    const float2 q2 = ((const float2*)(g_q + (size_t)n * 64))[lane];
    const int p0  = g_roff[n];
    const int p1  = g_roff[n + 1];
    const int deg = p1 - p0;
    const int nch = (deg + CH - 1) / CH;

    // 32-edge id window in lanes
    int ids = (p0 + lane < p1) ? g_esrc[p0 + lane] : 0;
    int win = 0;

    float2 a0 = make_float2(0.f, 0.f), a1 = a0, a2 = a0, a3 = a0;
    float z0 = 0.f;

    auto issue = [&](int cc) {
        const int first = cc * CH;
        if ((first >> 5) != win) {
            win = first >> 5;
            const int wb = p0 + win * 32;
            ids = (wb + lane < p1) ? g_esrc[wb + lane] : 0;
        }
#pragma unroll
        for (int j = 0; j < CH; j++) {
            const int e = cc * CH + j;
            const int id = __shfl_sync(0xffffffffu, ids, e & 31);
            if (e < deg) {
                const float* srcp = g_kw + (size_t)id * 128 + lane * 4;
                float* dstp = myring + (size_t)(e & (RING - 1)) * 128 + lane * 4;
                const unsigned sdst = (unsigned)__cvta_generic_to_shared(dstp);
                asm volatile("cp.async.cg.shared.global [%0], [%1], 16;"
                             :: "r"(sdst), "l"(srcp) : "memory");
            }
        }
        asm volatile("cp.async.commit_group;" ::: "memory");
    };

    if (nch > 0) issue(0);
    if (nch > 1) issue(1);

    for (int cc = 0; cc < nch; cc++) {
        if (cc + 2 <= nch) {
            asm volatile("cp.async.wait_group 1;" ::: "memory");
        } else {
            asm volatile("cp.async.wait_group 0;" ::: "memory");
        }
        __syncwarp();

#pragma unroll
        for (int j = 0; j < CH; j++) {
            const int e = cc * CH + j;
            if (e >= deg) break;
            const float* sp = myring + (size_t)(e & (RING - 1)) * 128;
            const float2 k2 = *(const float2*)(sp + 2 * lane);
            const float2 w2 = *(const float2*)(sp + 64 + 2 * lane);

            float prod = k2.x * q2.x + k2.y * q2.y;
            prod += __shfl_xor_sync(0xffffffffu, prod, 4);
            prod += __shfl_xor_sync(0xffffffffu, prod, 2);
            prod += __shfl_xor_sync(0xffffffffu, prod, 1);
            const float ew = __expf(prod);                        // own head
            const float eA = __shfl_xor_sync(0xffffffffu, ew, 8);  // head hh^1
            const float eB = __shfl_xor_sync(0xffffffffu, ew, 16); // head hh^2
            const float eC = __shfl_xor_sync(0xffffffffu, ew, 24); // head hh^3

            z0 += ew;
            a0.x += ew * w2.x; a0.y += ew * w2.y;
            a1.x += eA * w2.x; a1.y += eA * w2.y;
            a2.x += eB * w2.x; a2.y += eB * w2.y;
            a3.x += eC * w2.x; a3.y += eC * w2.y;
        }
        __syncwarp();
        if (cc + 2 < nch) issue(cc + 2);
    }

    // other heads' z from own-head lanes
    const float z1 = __shfl_xor_sync(0xffffffffu, z0, 8);
    const float z2 = __shfl_xor_sync(0xffffffffu, z0, 16);
    const float z3 = __shfl_xor_sync(0xffffffffu, z0, 24);

    const int hh = lane >> 3;
    const float i0 = (z0 > 0.f) ? 1.f / z0 : 0.f;
    const float i1 = (z1 > 0.f) ? 1.f / z1 : 0.f;
    const float i2 = (z2 > 0.f) ? 1.f / z2 : 0.f;
    const float i3 = (z3 > 0.f) ? 1.f / z3 : 0.f;

    const float2 bb = ((const float2*)b)[lane];   // features 2l, 2l+1
    float* op = out + (size_t)n * 256 + 2 * lane;

    *(float2*)(op + (size_t)(hh     ) * 64) = make_float2(a0.x * i0 + bb.x, a0.y * i0 + bb.y);
    *(float2*)(op + (size_t)(hh ^ 1) * 64) = make_float2(a1.x * i1 + bb.x, a1.y * i1 + bb.y);
    *(float2*)(op + (size_t)(hh ^ 2) * 64) = make_float2(a2.x * i2 + bb.x, a2.y * i2 + bb.y);
    *(float2*)(op + (size_t)(hh ^ 3) * 64) = make_float2(a3.x * i3 + bb.x, a3.y * i3 + bb.y);
}

// ---------------------------------------------------------------------------
extern "C" void kernel_launch(void* const* d_in, const int* in_sizes, int n_in,
                              void* d_out, int out_size)
{
    const float* h   = (const float*)d_in[0];
    const int*   src = (const int*)  d_in[1];
    const int*   dst = (const int*)  d_in[2];
    const float* Wk  = (const float*)d_in[3];
    const float* Wq  = (const float*)d_in[4];
    const float* Ww  = (const float*)d_in[5];
    const float* b   = (const float*)d_in[6];
    float*       out = (float*)d_out;

    const int N  = in_sizes[0] / 64;
    const int E  = in_sizes[1];
    const int nb = (N + 255) / 256;

    static void* cnt_ptr = nullptr;
    static void* state_ptr = nullptr;
    if (cnt_ptr == nullptr) {
        cudaGetSymbolAddress(&cnt_ptr, g_cnt);
        cudaGetSymbolAddress(&state_ptr, g_state);
    }

    cudaMemsetAsync(cnt_ptr, 0, (size_t)N * sizeof(int));
    cudaMemsetAsync(state_ptr, 0, (size_t)nb * sizeof(int));
    gemm_mma_hist_kernel<<<(N + 31) / 32, 192>>>(h, Wk, Wq, Ww, dst, N, E);
    scan_lb_kernel<<<nb, 256>>>(N, E);
    scatter_kernel<<<(E + 255) / 256, 256>>>(src, dst, E);
    gather_kernel<<<(N + 3) / 4, 128, 4 * RING * 128 * sizeof(float)>>>(b, out, N);
}

// round 10
// speedup vs baseline: 1.2454x; 1.2454x over previous
#include <cuda_runtime.h>

#define NN 100000
#define EE 1600000

// Scratch (allocation-free rule: __device__ globals)
__device__ float g_kw  [NN * 128];  // interleaved: [n][0:64]=k row, [n][64:128]=hw row
__device__ float g_q   [NN * 64];
__device__ int   g_cnt [NN];
__device__ int   g_roff[NN + 1];
__device__ int   g_cur [NN];
__device__ int   g_bsum[512];
__device__ int   g_boff[512];
__device__ int   g_esrc[EE];

// ---- tf32 helpers ----------------------------------------------------------
__device__ __forceinline__ unsigned to_tf32(float x)
{
    unsigned r; asm("cvt.rna.tf32.f32 %0, %1;" : "=r"(r) : "f"(x)); return r;
}
__device__ __forceinline__ void mma_tf32(float4& d, const unsigned* a, const unsigned* b)
{
    asm volatile(
        "mma.sync.aligned.m16n8k8.row.col.f32.tf32.tf32.f32 "
        "{%0,%1,%2,%3}, {%4,%5,%6,%7}, {%8,%9}, {%0,%1,%2,%3};"
        : "+f"(d.x), "+f"(d.y), "+f"(d.z), "+f"(d.w)
        : "r"(a[0]), "r"(a[1]), "r"(a[2]), "r"(a[3]), "r"(b[0]), "r"(b[1]));
}

// ---------------------------------------------------------------------------
// k = h@Wk, q = h@Wq, hw = h@W via 3xTF32 tensor-core MMA (fp32-class
// accuracy via hi/lo split). Pure gemm — runs on the SIDE stream, overlapped
// with the CSR chain. 192 threads = 6 warps = 3 matrices x 2 m-halves.
// ---------------------------------------------------------------------------
__global__ __launch_bounds__(192) void gemm_mma_kernel(
    const float* __restrict__ h,
    const float* __restrict__ Wk,
    const float* __restrict__ Wq,
    const float* __restrict__ Ww,
    int N)
{
    __shared__ float sA[32 * 72];        // sA[node][kdim]
    __shared__ float sW[3 * 64 * 72];    // sW[sel][kdim][col]

    const int tid = threadIdx.x;

    for (int idx = tid; idx < 64 * 64; idx += 192) {
        const int i = idx >> 6, c = idx & 63;
        sW[0 * 64 * 72 + i * 72 + c] = Wk[idx];
        sW[1 * 64 * 72 + i * 72 + c] = Wq[idx];
        sW[2 * 64 * 72 + i * 72 + c] = Ww[idx];
    }
    const int base = blockIdx.x * 32;
    for (int idx = tid; idx < 32 * 64; idx += 192) {
        const int n = idx >> 6, c = idx & 63;
        const int gn = base + n;
        sA[n * 72 + c] = (gn < N) ? h[(size_t)gn * 64 + c] : 0.f;
    }
    __syncthreads();

    const int wid  = tid >> 5;
    const int lane = tid & 31;
    const int sel  = wid >> 1;          // 0:Wk 1:Wq 2:Ww
    const int mh   = wid & 1;           // m-half (16 nodes)
    const int g    = lane >> 2;         // 0..7
    const int t4   = lane & 3;          // 0..3

    float4 acc[8];
#pragma unroll
    for (int nt = 0; nt < 8; nt++) acc[nt] = make_float4(0.f, 0.f, 0.f, 0.f);

    const float* wm = sW + sel * 64 * 72;

#pragma unroll
    for (int ks = 0; ks < 8; ks++) {
        const int r0 = (mh * 16 + g) * 72 + ks * 8 + t4;
        const int r1 = (mh * 16 + g + 8) * 72 + ks * 8 + t4;
        const float a0f = sA[r0],     a1f = sA[r1];
        const float a2f = sA[r0 + 4], a3f = sA[r1 + 4];

        unsigned ahi[4], alo[4];
        ahi[0] = to_tf32(a0f); alo[0] = to_tf32(a0f - __uint_as_float(ahi[0]));
        ahi[1] = to_tf32(a1f); alo[1] = to_tf32(a1f - __uint_as_float(ahi[1]));
        ahi[2] = to_tf32(a2f); alo[2] = to_tf32(a2f - __uint_as_float(ahi[2]));
        ahi[3] = to_tf32(a3f); alo[3] = to_tf32(a3f - __uint_as_float(ahi[3]));

#pragma unroll
        for (int nt = 0; nt < 8; nt++) {
            const float b0f = wm[(ks * 8 + t4) * 72 + nt * 8 + g];
            const float b1f = wm[(ks * 8 + t4 + 4) * 72 + nt * 8 + g];
            unsigned bhi[2], blo[2];
            bhi[0] = to_tf32(b0f); blo[0] = to_tf32(b0f - __uint_as_float(bhi[0]));
            bhi[1] = to_tf32(b1f); blo[1] = to_tf32(b1f - __uint_as_float(bhi[1]));

            mma_tf32(acc[nt], ahi, bhi);
            mma_tf32(acc[nt], ahi, blo);
            mma_tf32(acc[nt], alo, bhi);
        }
    }

    const int gn0 = base + mh * 16 + g;
    const int gn1 = gn0 + 8;
#pragma unroll
    for (int nt = 0; nt < 8; nt++) {
        const int col = nt * 8 + t4 * 2;
        if (sel == 0) {
            if (gn0 < N) *(float2*)&g_kw[(size_t)gn0 * 128 + col] = make_float2(acc[nt].x, acc[nt].y);
            if (gn1 < N) *(float2*)&g_kw[(size_t)gn1 * 128 + col] = make_float2(acc[nt].z, acc[nt].w);
        } else if (sel == 1) {
            if (gn0 < N) *(float2*)&g_q[(size_t)gn0 * 64 + col] = make_float2(acc[nt].x, acc[nt].y);
            if (gn1 < N) *(float2*)&g_q[(size_t)gn1 * 64 + col] = make_float2(acc[nt].z, acc[nt].w);
        } else {
            if (gn0 < N) *(float2*)&g_kw[(size_t)gn0 * 128 + 64 + col] = make_float2(acc[nt].x, acc[nt].y);
            if (gn1 < N) *(float2*)&g_kw[(size_t)gn1 * 128 + 64 + col] = make_float2(acc[nt].z, acc[nt].w);
        }
    }
}

// ---------------------------------------------------------------------------
// Histogram of dst (int4 loads)
// ---------------------------------------------------------------------------
__global__ void hist_kernel(const int* __restrict__ dst, int E)
{
    const int i4 = (blockIdx.x * blockDim.x + threadIdx.x) * 4;
    if (i4 + 3 < E) {
        const int4 d = *(const int4*)(dst + i4);
        atomicAdd(&g_cnt[d.x], 1);
        atomicAdd(&g_cnt[d.y], 1);
        atomicAdd(&g_cnt[d.z], 1);
        atomicAdd(&g_cnt[d.w], 1);
    } else {
        for (int j = i4; j < E; j++) atomicAdd(&g_cnt[dst[j]], 1);
    }
}

// ---------------------------------------------------------------------------
// Three-kernel shuffle-based exclusive scan (NO spinning — safe to run
// concurrently with the side-stream gemm).
// ---------------------------------------------------------------------------
__global__ __launch_bounds__(256) void scan1_kernel(int N)
{
    __shared__ int wsum[8];
    const int t = threadIdx.x, lane = t & 31, wd = t >> 5;
    const int i = blockIdx.x * 256 + t;
    const int v = (i < N) ? g_cnt[i] : 0;
    int x = v;
#pragma unroll
    for (int off = 1; off < 32; off <<= 1) {
        int y = __shfl_up_sync(0xffffffffu, x, off);
        if (lane >= off) x += y;
    }
    if (lane == 31) wsum[wd] = x;
    __syncthreads();
    if (t < 8) {
        int w = wsum[t];
        int xs = w;
#pragma unroll
        for (int off = 1; off < 8; off <<= 1) {
            int y = __shfl_up_sync(0x000000ffu, xs, off);
            if (t >= off) xs += y;
        }
        wsum[t] = xs - w;                       // exclusive warp offset
        if (t == 7) g_bsum[blockIdx.x] = xs;    // block total
    }
    __syncthreads();
    if (i < N) g_roff[i] = x - v + wsum[wd];
}

__global__ __launch_bounds__(512) void scan2_kernel(int nb)
{
    __shared__ int wsum[16];
    const int t = threadIdx.x, lane = t & 31, wd = t >> 5;
    const int v = (t < nb) ? g_bsum[t] : 0;
    int x = v;
#pragma unroll
    for (int off = 1; off < 32; off <<= 1) {
        int y = __shfl_up_sync(0xffffffffu, x, off);
        if (lane >= off) x += y;
    }
    if (lane == 31) wsum[wd] = x;
    __syncthreads();
    if (t < 16) {
        int w = wsum[t];
        int xs = w;
#pragma unroll
        for (int off = 1; off < 16; off <<= 1) {
            int y = __shfl_up_sync(0x0000ffffu, xs, off);
            if (t >= off) xs += y;
        }
        wsum[t] = xs - w;
    }
    __syncthreads();
    if (t < nb) g_boff[t] = x - v + wsum[wd];
}

__global__ void scan3_kernel(int N, int E)
{
    int i = blockIdx.x * blockDim.x + threadIdx.x;
    if (i < N) {
        int r = g_roff[i] + g_boff[i >> 8];
        g_roff[i] = r;
        g_cur[i]  = r;
    }
    if (i == 0) g_roff[N] = E;
}

// ---------------------------------------------------------------------------
// Scatter src ids into CSR order (int4 loads)
// ---------------------------------------------------------------------------
__global__ void scatter_kernel(const int* __restrict__ src,
                               const int* __restrict__ dst, int E)
{
    const int i4 = (blockIdx.x * blockDim.x + threadIdx.x) * 4;
    if (i4 + 3 < E) {
        const int4 d = *(const int4*)(dst + i4);
        const int4 s = *(const int4*)(src + i4);
        g_esrc[atomicAdd(&g_cur[d.x], 1)] = s.x;
        g_esrc[atomicAdd(&g_cur[d.y], 1)] = s.y;
        g_esrc[atomicAdd(&g_cur[d.z], 1)] = s.z;
        g_esrc[atomicAdd(&g_cur[d.w], 1)] = s.w;
    } else {
        for (int j = i4; j < E; j++)
            g_esrc[atomicAdd(&g_cur[dst[j]], 1)] = src[j];
    }
}

// ---------------------------------------------------------------------------
// Fused edge-softmax + aggregation (R5-proven form, frozen).
// One warp per destination node; 512 B/edge; 1-deep register prefetch.
// ---------------------------------------------------------------------------
__global__ __launch_bounds__(256) void gather_kernel(
    const float* __restrict__ b,
    float* __restrict__ out,
    int N)
{
    const int w    = (blockIdx.x * 256 + threadIdx.x) >> 5;
    const int lane = threadIdx.x & 31;
    if (w >= N) return;
    const int n = w;

    const float2 q2 = ((const float2*)(g_q + (size_t)n * 64))[lane];
    const int p0 = g_roff[n];
    const int p1 = g_roff[n + 1];

    float2 acc0 = make_float2(0.f, 0.f), acc1 = acc0, acc2 = acc0, acc3 = acc0;
    float z0 = 0.f, z1 = 0.f, z2 = 0.f, z3 = 0.f;

    if (p0 < p1) {
        int s = g_esrc[p0];
        const float2* kp = (const float2*)(g_kw + (size_t)s * 128);
        float2 k2 = kp[lane];
        float2 w2 = kp[lane + 32];

        for (int p = p0; p < p1; p++) {
            float2 k2n = k2, w2n = w2;
            if (p + 1 < p1) {
                int sn = g_esrc[p + 1];
                const float2* kpn = (const float2*)(g_kw + (size_t)sn * 128);
                k2n = kpn[lane];
                w2n = kpn[lane + 32];
            }

            float prod = k2.x * q2.x + k2.y * q2.y;
            prod += __shfl_xor_sync(0xffffffffu, prod, 4);
            prod += __shfl_xor_sync(0xffffffffu, prod, 2);
            prod += __shfl_xor_sync(0xffffffffu, prod, 1);
            const float pe = __expf(prod);
            const float e0 = __shfl_sync(0xffffffffu, pe, 0);
            const float e1 = __shfl_sync(0xffffffffu, pe, 8);
            const float e2 = __shfl_sync(0xffffffffu, pe, 16);
            const float e3 = __shfl_sync(0xffffffffu, pe, 24);

            z0 += e0; z1 += e1; z2 += e2; z3 += e3;
            acc0.x += e0 * w2.x; acc0.y += e0 * w2.y;
            acc1.x += e1 * w2.x; acc1.y += e1 * w2.y;
            acc2.x += e2 * w2.x; acc2.y += e2 * w2.y;
            acc3.x += e3 * w2.x; acc3.y += e3 * w2.y;

            k2 = k2n; w2 = w2n;
        }
    }

    const float i0 = (z0 > 0.f) ? 1.f / z0 : 0.f;
    const float i1 = (z1 > 0.f) ? 1.f / z1 : 0.f;
    const float i2 = (z2 > 0.f) ? 1.f / z2 : 0.f;
    const float i3 = (z3 > 0.f) ? 1.f / z3 : 0.f;

    const float2 bb = ((const float2*)b)[lane];
    float* op = out + (size_t)n * 256;
    ((float2*)(op      ))[lane] = make_float2(acc0.x * i0 + bb.x, acc0.y * i0 + bb.y);
    ((float2*)(op +  64))[lane] = make_float2(acc1.x * i1 + bb.x, acc1.y * i1 + bb.y);
    ((float2*)(op + 128))[lane] = make_float2(acc2.x * i2 + bb.x, acc2.y * i2 + bb.y);
    ((float2*)(op + 192))[lane] = make_float2(acc3.x * i3 + bb.x, acc3.y * i3 + bb.y);
}

// ---------------------------------------------------------------------------
extern "C" void kernel_launch(void* const* d_in, const int* in_sizes, int n_in,
                              void* d_out, int out_size)
{
    const float* h   = (const float*)d_in[0];
    const int*   src = (const int*)  d_in[1];
    const int*   dst = (const int*)  d_in[2];
    const float* Wk  = (const float*)d_in[3];
    const float* Wq  = (const float*)d_in[4];
    const float* Ww  = (const float*)d_in[5];
    const float* b   = (const float*)d_in[6];
    float*       out = (float*)d_out;

    const int N  = in_sizes[0] / 64;
    const int E  = in_sizes[1];
    const int nb = (N + 255) / 256;

    static void* cnt_ptr = nullptr;
    static cudaStream_t sideStream = nullptr;
    static cudaEvent_t  evFork = nullptr, evJoin = nullptr;
    if (cnt_ptr == nullptr) {
        cudaGetSymbolAddress(&cnt_ptr, g_cnt);
        cudaStreamCreateWithFlags(&sideStream, cudaStreamNonBlocking);
        cudaEventCreateWithFlags(&evFork, cudaEventDisableTiming);
        cudaEventCreateWithFlags(&evJoin, cudaEventDisableTiming);
    }

    // Fork: pure gemm (h,W only) overlaps the whole CSR chain (src,dst only).
    cudaEventRecord(evFork, 0);
    cudaStreamWaitEvent(sideStream, evFork, 0);
    gemm_mma_kernel<<<(N + 31) / 32, 192, 0, sideStream>>>(h, Wk, Wq, Ww, N);
    cudaEventRecord(evJoin, sideStream);

    cudaMemsetAsync(cnt_ptr, 0, (size_t)N * sizeof(int));
    hist_kernel<<<(E / 4 + 255) / 256, 256>>>(dst, E);
    scan1_kernel<<<nb, 256>>>(N);
    scan2_kernel<<<1, 512>>>(nb);
    scan3_kernel<<<(N + 255) / 256, 256>>>(N, E);
    scatter_kernel<<<(E / 4 + 255) / 256, 256>>>(src, dst, E);

    cudaStreamWaitEvent(0, evJoin, 0);
    gather_kernel<<<(N + 7) / 8, 256>>>(b, out, N);
}

// round 11
// speedup vs baseline: 1.2517x; 1.0051x over previous
#include <cuda_runtime.h>

#define NN 100000
#define EE 1600000

// Scratch (allocation-free rule: __device__ globals)
__device__ float g_kw  [NN * 128];  // interleaved: [n][0:64]=k row, [n][64:128]=hw row
__device__ float g_q   [NN * 64];
__device__ int   g_cnt [NN];
__device__ int   g_roff[NN + 1];
__device__ int   g_cur [NN];
__device__ int   g_bsum[512];
__device__ int   g_boff[512];
__device__ int   g_esrc[EE];

// ---- tf32 helpers ----------------------------------------------------------
__device__ __forceinline__ unsigned to_tf32(float x)
{
    unsigned r; asm("cvt.rna.tf32.f32 %0, %1;" : "=r"(r) : "f"(x)); return r;
}
__device__ __forceinline__ void mma_tf32(float4& d, const unsigned* a, const unsigned* b)
{
    asm volatile(
        "mma.sync.aligned.m16n8k8.row.col.f32.tf32.tf32.f32 "
        "{%0,%1,%2,%3}, {%4,%5,%6,%7}, {%8,%9}, {%0,%1,%2,%3};"
        : "+f"(d.x), "+f"(d.y), "+f"(d.z), "+f"(d.w)
        : "r"(a[0]), "r"(a[1]), "r"(a[2]), "r"(a[3]), "r"(b[0]), "r"(b[1]));
}

// ---------------------------------------------------------------------------
// k = h@Wk, q = h@Wq, hw = h@W via 3xTF32 tensor-core MMA (fp32-class
// accuracy via hi/lo split). Runs on the SIDE stream, overlapped with the CSR
// chain. 192 threads = 6 warps = 3 matrices x 2 m-halves. (R10-proven.)
// ---------------------------------------------------------------------------
__global__ __launch_bounds__(192) void gemm_mma_kernel(
    const float* __restrict__ h,
    const float* __restrict__ Wk,
    const float* __restrict__ Wq,
    const float* __restrict__ Ww,
    int N)
{
    __shared__ float sA[32 * 72];        // sA[node][kdim]
    __shared__ float sW[3 * 64 * 72];    // sW[sel][kdim][col]

    const int tid = threadIdx.x;

    for (int idx = tid; idx < 64 * 64; idx += 192) {
        const int i = idx >> 6, c = idx & 63;
        sW[0 * 64 * 72 + i * 72 + c] = Wk[idx];
        sW[1 * 64 * 72 + i * 72 + c] = Wq[idx];
        sW[2 * 64 * 72 + i * 72 + c] = Ww[idx];
    }
    const int base = blockIdx.x * 32;
    for (int idx = tid; idx < 32 * 64; idx += 192) {
        const int n = idx >> 6, c = idx & 63;
        const int gn = base + n;
        sA[n * 72 + c] = (gn < N) ? h[(size_t)gn * 64 + c] : 0.f;
    }
    __syncthreads();

    const int wid  = tid >> 5;
    const int lane = tid & 31;
    const int sel  = wid >> 1;          // 0:Wk 1:Wq 2:Ww
    const int mh   = wid & 1;           // m-half (16 nodes)
    const int g    = lane >> 2;         // 0..7
    const int t4   = lane & 3;          // 0..3

    float4 acc[8];
#pragma unroll
    for (int nt = 0; nt < 8; nt++) acc[nt] = make_float4(0.f, 0.f, 0.f, 0.f);

    const float* wm = sW + sel * 64 * 72;

#pragma unroll
    for (int ks = 0; ks < 8; ks++) {
        const int r0 = (mh * 16 + g) * 72 + ks * 8 + t4;
        const int r1 = (mh * 16 + g + 8) * 72 + ks * 8 + t4;
        const float a0f = sA[r0],     a1f = sA[r1];
        const float a2f = sA[r0 + 4], a3f = sA[r1 + 4];

        unsigned ahi[4], alo[4];
        ahi[0] = to_tf32(a0f); alo[0] = to_tf32(a0f - __uint_as_float(ahi[0]));
        ahi[1] = to_tf32(a1f); alo[1] = to_tf32(a1f - __uint_as_float(ahi[1]));
        ahi[2] = to_tf32(a2f); alo[2] = to_tf32(a2f - __uint_as_float(ahi[2]));
        ahi[3] = to_tf32(a3f); alo[3] = to_tf32(a3f - __uint_as_float(ahi[3]));

#pragma unroll
        for (int nt = 0; nt < 8; nt++) {
            const float b0f = wm[(ks * 8 + t4) * 72 + nt * 8 + g];
            const float b1f = wm[(ks * 8 + t4 + 4) * 72 + nt * 8 + g];
            unsigned bhi[2], blo[2];
            bhi[0] = to_tf32(b0f); blo[0] = to_tf32(b0f - __uint_as_float(bhi[0]));
            bhi[1] = to_tf32(b1f); blo[1] = to_tf32(b1f - __uint_as_float(bhi[1]));

            mma_tf32(acc[nt], ahi, bhi);
            mma_tf32(acc[nt], ahi, blo);
            mma_tf32(acc[nt], alo, bhi);
        }
    }

    const int gn0 = base + mh * 16 + g;
    const int gn1 = gn0 + 8;
#pragma unroll
    for (int nt = 0; nt < 8; nt++) {
        const int col = nt * 8 + t4 * 2;
        if (sel == 0) {
            if (gn0 < N) *(float2*)&g_kw[(size_t)gn0 * 128 + col] = make_float2(acc[nt].x, acc[nt].y);
            if (gn1 < N) *(float2*)&g_kw[(size_t)gn1 * 128 + col] = make_float2(acc[nt].z, acc[nt].w);
        } else if (sel == 1) {
            if (gn0 < N) *(float2*)&g_q[(size_t)gn0 * 64 + col] = make_float2(acc[nt].x, acc[nt].y);
            if (gn1 < N) *(float2*)&g_q[(size_t)gn1 * 64 + col] = make_float2(acc[nt].z, acc[nt].w);
        } else {
            if (gn0 < N) *(float2*)&g_kw[(size_t)gn0 * 128 + 64 + col] = make_float2(acc[nt].x, acc[nt].y);
            if (gn1 < N) *(float2*)&g_kw[(size_t)gn1 * 128 + 64 + col] = make_float2(acc[nt].z, acc[nt].w);
        }
    }
}

// ---------------------------------------------------------------------------
// Histogram of dst (int4 loads)
// ---------------------------------------------------------------------------
__global__ void hist_kernel(const int* __restrict__ dst, int E)
{
    const int i4 = (blockIdx.x * blockDim.x + threadIdx.x) * 4;
    if (i4 + 3 < E) {
        const int4 d = *(const int4*)(dst + i4);
        atomicAdd(&g_cnt[d.x], 1);
        atomicAdd(&g_cnt[d.y], 1);
        atomicAdd(&g_cnt[d.z], 1);
        atomicAdd(&g_cnt[d.w], 1);
    } else {
        for (int j = i4; j < E; j++) atomicAdd(&g_cnt[dst[j]], 1);
    }
}

// ---------------------------------------------------------------------------
// Three-kernel shuffle-based exclusive scan (no spinning — fork-safe).
// ---------------------------------------------------------------------------
__global__ __launch_bounds__(256) void scan1_kernel(int N)
{
    __shared__ int wsum[8];
    const int t = threadIdx.x, lane = t & 31, wd = t >> 5;
    const int i = blockIdx.x * 256 + t;
    const int v = (i < N) ? g_cnt[i] : 0;
    int x = v;
#pragma unroll
    for (int off = 1; off < 32; off <<= 1) {
        int y = __shfl_up_sync(0xffffffffu, x, off);
        if (lane >= off) x += y;
    }
    if (lane == 31) wsum[wd] = x;
    __syncthreads();
    if (t < 8) {
        int w = wsum[t];
        int xs = w;
#pragma unroll
        for (int off = 1; off < 8; off <<= 1) {
            int y = __shfl_up_sync(0x000000ffu, xs, off);
            if (t >= off) xs += y;
        }
        wsum[t] = xs - w;                       // exclusive warp offset
        if (t == 7) g_bsum[blockIdx.x] = xs;    // block total
    }
    __syncthreads();
    if (i < N) g_roff[i] = x - v + wsum[wd];
}

__global__ __launch_bounds__(512) void scan2_kernel(int nb)
{
    __shared__ int wsum[16];
    const int t = threadIdx.x, lane = t & 31, wd = t >> 5;
    const int v = (t < nb) ? g_bsum[t] : 0;
    int x = v;
#pragma unroll
    for (int off = 1; off < 32; off <<= 1) {
        int y = __shfl_up_sync(0xffffffffu, x, off);
        if (lane >= off) x += y;
    }
    if (lane == 31) wsum[wd] = x;
    __syncthreads();
    if (t < 16) {
        int w = wsum[t];
        int xs = w;
#pragma unroll
        for (int off = 1; off < 16; off <<= 1) {
            int y = __shfl_up_sync(0x0000ffffu, xs, off);
            if (t >= off) xs += y;
        }
        wsum[t] = xs - w;
    }
    __syncthreads();
    if (t < nb) g_boff[t] = x - v + wsum[wd];
}

__global__ void scan3_kernel(int N, int E)
{
    int i = blockIdx.x * blockDim.x + threadIdx.x;
    if (i < N) {
        int r = g_roff[i] + g_boff[i >> 8];
        g_roff[i] = r;
        g_cur[i]  = r;
    }
    if (i == 0) g_roff[N] = E;
}

// ---------------------------------------------------------------------------
// Scatter src ids into CSR order (int4 loads)
// ---------------------------------------------------------------------------
__global__ void scatter_kernel(const int* __restrict__ src,
                               const int* __restrict__ dst, int E)
{
    const int i4 = (blockIdx.x * blockDim.x + threadIdx.x) * 4;
    if (i4 + 3 < E) {
        const int4 d = *(const int4*)(dst + i4);
        const int4 s = *(const int4*)(src + i4);
        g_esrc[atomicAdd(&g_cur[d.x], 1)] = s.x;
        g_esrc[atomicAdd(&g_cur[d.y], 1)] = s.y;
        g_esrc[atomicAdd(&g_cur[d.z], 1)] = s.z;
        g_esrc[atomicAdd(&g_cur[d.w], 1)] = s.w;
    } else {
        for (int j = i4; j < E; j++)
            g_esrc[atomicAdd(&g_cur[dst[j]], 1)] = src[j];
    }
}

// ---------------------------------------------------------------------------
// Fused edge-softmax + aggregation. One warp per destination node, R5's
// direct-LDG 1-deep prefetch, R9's (correctness-proven) lean consumption:
// lane l owns features 2l..2l+1; own head hh = l>>3; dot reduce = 3 xor
// shuffles within the 8-lane group; other heads' weights = 3 relative xor
// shuffles (acc_j belongs to head hh^j); z for other heads recovered AFTER
// the loop. ~22 warp-instrs/edge vs R5's ~30; identical 512 B/edge traffic.
// ---------------------------------------------------------------------------
__global__ __launch_bounds__(256) void gather_kernel(
    const float* __restrict__ b,
    float* __restrict__ out,
    int N)
{
    const int n    = (blockIdx.x * 256 + threadIdx.x) >> 5;
    const int lane = threadIdx.x & 31;
    if (n >= N) return;
    const int hh = lane >> 3;   // own head

    const float2 q2 = ((const float2*)(g_q + (size_t)n * 64))[lane];
    const int p0 = g_roff[n];
    const int p1 = g_roff[n + 1];

    float2 a0 = make_float2(0.f, 0.f), a1 = a0, a2 = a0, a3 = a0;
    float z0 = 0.f;

    if (p0 < p1) {
        int s = g_esrc[p0];
        const float2* kp = (const float2*)(g_kw + (size_t)s * 128);
        float2 k2 = kp[lane];
        float2 w2 = kp[lane + 32];

        for (int p = p0; p < p1; p++) {
            float2 k2n = k2, w2n = w2;
            if (p + 1 < p1) {
                const int sn = g_esrc[p + 1];
                const float2* kpn = (const float2*)(g_kw + (size_t)sn * 128);
                k2n = kpn[lane];
                w2n = kpn[lane + 32];
            }

            float prod = k2.x * q2.x + k2.y * q2.y;
            prod += __shfl_xor_sync(0xffffffffu, prod, 4);
            prod += __shfl_xor_sync(0xffffffffu, prod, 2);
            prod += __shfl_xor_sync(0xffffffffu, prod, 1);
            const float ew = __expf(prod);                         // own head
            const float eA = __shfl_xor_sync(0xffffffffu, ew, 8);  // head hh^1
            const float eB = __shfl_xor_sync(0xffffffffu, ew, 16); // head hh^2
            const float eC = __shfl_xor_sync(0xffffffffu, ew, 24); // head hh^3

            z0 += ew;
            a0.x += ew * w2.x; a0.y += ew * w2.y;
            a1.x += eA * w2.x; a1.y += eA * w2.y;
            a2.x += eB * w2.x; a2.y += eB * w2.y;
            a3.x += eC * w2.x; a3.y += eC * w2.y;

            k2 = k2n; w2 = w2n;
        }
    }

    // other heads' z from own-head lanes
    const float z1 = __shfl_xor_sync(0xffffffffu, z0, 8);
    const float z2 = __shfl_xor_sync(0xffffffffu, z0, 16);
    const float z3 = __shfl_xor_sync(0xffffffffu, z0, 24);

    const float i0 = (z0 > 0.f) ? 1.f / z0 : 0.f;
    const float i1 = (z1 > 0.f) ? 1.f / z1 : 0.f;
    const float i2 = (z2 > 0.f) ? 1.f / z2 : 0.f;
    const float i3 = (z3 > 0.f) ? 1.f / z3 : 0.f;

    const float2 bb = ((const float2*)b)[lane];   // features 2l, 2l+1
    float* op = out + (size_t)n * 256 + 2 * lane;

    *(float2*)(op + (size_t)(hh     ) * 64) = make_float2(a0.x * i0 + bb.x, a0.y * i0 + bb.y);
    *(float2*)(op + (size_t)(hh ^ 1) * 64) = make_float2(a1.x * i1 + bb.x, a1.y * i1 + bb.y);
    *(float2*)(op + (size_t)(hh ^ 2) * 64) = make_float2(a2.x * i2 + bb.x, a2.y * i2 + bb.y);
    *(float2*)(op + (size_t)(hh ^ 3) * 64) = make_float2(a3.x * i3 + bb.x, a3.y * i3 + bb.y);
}

// ---------------------------------------------------------------------------
extern "C" void kernel_launch(void* const* d_in, const int* in_sizes, int n_in,
                              void* d_out, int out_size)
{
    const float* h   = (const float*)d_in[0];
    const int*   src = (const int*)  d_in[1];
    const int*   dst = (const int*)  d_in[2];
    const float* Wk  = (const float*)d_in[3];
    const float* Wq  = (const float*)d_in[4];
    const float* Ww  = (const float*)d_in[5];
    const float* b   = (const float*)d_in[6];
    float*       out = (float*)d_out;

    const int N  = in_sizes[0] / 64;
    const int E  = in_sizes[1];
    const int nb = (N + 255) / 256;

    static void* cnt_ptr = nullptr;
    static cudaStream_t sideStream = nullptr;
    static cudaEvent_t  evFork = nullptr, evJoin = nullptr;
    if (cnt_ptr == nullptr) {
        cudaGetSymbolAddress(&cnt_ptr, g_cnt);
        cudaStreamCreateWithFlags(&sideStream, cudaStreamNonBlocking);
        cudaEventCreateWithFlags(&evFork, cudaEventDisableTiming);
        cudaEventCreateWithFlags(&evJoin, cudaEventDisableTiming);
    }

    // Fork: pure gemm (h,W only) overlaps the whole CSR chain (src,dst only).
    cudaEventRecord(evFork, 0);
    cudaStreamWaitEvent(sideStream, evFork, 0);
    gemm_mma_kernel<<<(N + 31) / 32, 192, 0, sideStream>>>(h, Wk, Wq, Ww, N);
    cudaEventRecord(evJoin, sideStream);

    cudaMemsetAsync(cnt_ptr, 0, (size_t)N * sizeof(int));
    hist_kernel<<<(E / 4 + 255) / 256, 256>>>(dst, E);
    scan1_kernel<<<nb, 256>>>(N);
    scan2_kernel<<<1, 512>>>(nb);
    scan3_kernel<<<(N + 255) / 256, 256>>>(N, E);
    scatter_kernel<<<(E / 4 + 255) / 256, 256>>>(src, dst, E);

    cudaStreamWaitEvent(0, evJoin, 0);
    gather_kernel<<<(N + 7) / 8, 256>>>(b, out, N);
}

// round 12
// speedup vs baseline: 1.3581x; 1.0850x over previous
#include <cuda_runtime.h>

#define NN 100000
#define EE 1600000

// Scratch (allocation-free rule: __device__ globals)
__device__ float g_kw  [NN * 128];  // interleaved: [n][0:64]=k row, [n][64:128]=hw row
__device__ float g_q   [NN * 64];
__device__ int   g_cnt [NN];
__device__ int   g_roff[NN + 1];
__device__ int   g_cur [NN];
__device__ int   g_bsum[512];
__device__ int   g_esrc[EE];

// ---- tf32 helpers ----------------------------------------------------------
__device__ __forceinline__ unsigned to_tf32(float x)
{
    unsigned r; asm("cvt.rna.tf32.f32 %0, %1;" : "=r"(r) : "f"(x)); return r;
}
__device__ __forceinline__ void mma_tf32(float4& d, const unsigned* a, const unsigned* b)
{
    asm volatile(
        "mma.sync.aligned.m16n8k8.row.col.f32.tf32.tf32.f32 "
        "{%0,%1,%2,%3}, {%4,%5,%6,%7}, {%8,%9}, {%0,%1,%2,%3};"
        : "+f"(d.x), "+f"(d.y), "+f"(d.z), "+f"(d.w)
        : "r"(a[0]), "r"(a[1]), "r"(a[2]), "r"(a[3]), "r"(b[0]), "r"(b[1]));
}

// ---------------------------------------------------------------------------
// k = h@Wk, q = h@Wq, hw = h@W via 3xTF32 tensor-core MMA (fp32-class
// accuracy via hi/lo split). Runs on the SIDE stream, overlapped with the CSR
// chain. 192 threads = 6 warps = 3 matrices x 2 m-halves. (R10/R11-proven.)
// ---------------------------------------------------------------------------
__global__ __launch_bounds__(192) void gemm_mma_kernel(
    const float* __restrict__ h,
    const float* __restrict__ Wk,
    const float* __restrict__ Wq,
    const float* __restrict__ Ww,
    int N)
{
    __shared__ float sA[32 * 72];        // sA[node][kdim]
    __shared__ float sW[3 * 64 * 72];    // sW[sel][kdim][col]

    const int tid = threadIdx.x;

    for (int idx = tid; idx < 64 * 64; idx += 192) {
        const int i = idx >> 6, c = idx & 63;
        sW[0 * 64 * 72 + i * 72 + c] = Wk[idx];
        sW[1 * 64 * 72 + i * 72 + c] = Wq[idx];
        sW[2 * 64 * 72 + i * 72 + c] = Ww[idx];
    }
    const int base = blockIdx.x * 32;
    for (int idx = tid; idx < 32 * 64; idx += 192) {
        const int n = idx >> 6, c = idx & 63;
        const int gn = base + n;
        sA[n * 72 + c] = (gn < N) ? h[(size_t)gn * 64 + c] : 0.f;
    }
    __syncthreads();

    const int wid  = tid >> 5;
    const int lane = tid & 31;
    const int sel  = wid >> 1;          // 0:Wk 1:Wq 2:Ww
    const int mh   = wid & 1;           // m-half (16 nodes)
    const int g    = lane >> 2;         // 0..7
    const int t4   = lane & 3;          // 0..3

    float4 acc[8];
#pragma unroll
    for (int nt = 0; nt < 8; nt++) acc[nt] = make_float4(0.f, 0.f, 0.f, 0.f);

    const float* wm = sW + sel * 64 * 72;

#pragma unroll
    for (int ks = 0; ks < 8; ks++) {
        const int r0 = (mh * 16 + g) * 72 + ks * 8 + t4;
        const int r1 = (mh * 16 + g + 8) * 72 + ks * 8 + t4;
        const float a0f = sA[r0],     a1f = sA[r1];
        const float a2f = sA[r0 + 4], a3f = sA[r1 + 4];

        unsigned ahi[4], alo[4];
        ahi[0] = to_tf32(a0f); alo[0] = to_tf32(a0f - __uint_as_float(ahi[0]));
        ahi[1] = to_tf32(a1f); alo[1] = to_tf32(a1f - __uint_as_float(ahi[1]));
        ahi[2] = to_tf32(a2f); alo[2] = to_tf32(a2f - __uint_as_float(ahi[2]));
        ahi[3] = to_tf32(a3f); alo[3] = to_tf32(a3f - __uint_as_float(ahi[3]));

#pragma unroll
        for (int nt = 0; nt < 8; nt++) {
            const float b0f = wm[(ks * 8 + t4) * 72 + nt * 8 + g];
            const float b1f = wm[(ks * 8 + t4 + 4) * 72 + nt * 8 + g];
            unsigned bhi[2], blo[2];
            bhi[0] = to_tf32(b0f); blo[0] = to_tf32(b0f - __uint_as_float(bhi[0]));
            bhi[1] = to_tf32(b1f); blo[1] = to_tf32(b1f - __uint_as_float(bhi[1]));

            mma_tf32(acc[nt], ahi, bhi);
            mma_tf32(acc[nt], ahi, blo);
            mma_tf32(acc[nt], alo, bhi);
        }
    }

    const int gn0 = base + mh * 16 + g;
    const int gn1 = gn0 + 8;
#pragma unroll
    for (int nt = 0; nt < 8; nt++) {
        const int col = nt * 8 + t4 * 2;
        if (sel == 0) {
            if (gn0 < N) *(float2*)&g_kw[(size_t)gn0 * 128 + col] = make_float2(acc[nt].x, acc[nt].y);
            if (gn1 < N) *(float2*)&g_kw[(size_t)gn1 * 128 + col] = make_float2(acc[nt].z, acc[nt].w);
        } else if (sel == 1) {
            if (gn0 < N) *(float2*)&g_q[(size_t)gn0 * 64 + col] = make_float2(acc[nt].x, acc[nt].y);
            if (gn1 < N) *(float2*)&g_q[(size_t)gn1 * 64 + col] = make_float2(acc[nt].z, acc[nt].w);
        } else {
            if (gn0 < N) *(float2*)&g_kw[(size_t)gn0 * 128 + 64 + col] = make_float2(acc[nt].x, acc[nt].y);
            if (gn1 < N) *(float2*)&g_kw[(size_t)gn1 * 128 + 64 + col] = make_float2(acc[nt].z, acc[nt].w);
        }
    }
}

// ---------------------------------------------------------------------------
// Histogram of dst (int4 loads)
// ---------------------------------------------------------------------------
__global__ void hist_kernel(const int* __restrict__ dst, int E)
{
    const int i4 = (blockIdx.x * blockDim.x + threadIdx.x) * 4;
    if (i4 + 3 < E) {
        const int4 d = *(const int4*)(dst + i4);
        atomicAdd(&g_cnt[d.x], 1);
        atomicAdd(&g_cnt[d.y], 1);
        atomicAdd(&g_cnt[d.z], 1);
        atomicAdd(&g_cnt[d.w], 1);
    } else {
        for (int j = i4; j < E; j++) atomicAdd(&g_cnt[dst[j]], 1);
    }
}

// ---------------------------------------------------------------------------
// Scan stage 1: per-block exclusive scan + block totals (no spinning).
// ---------------------------------------------------------------------------
__global__ __launch_bounds__(256) void scan1_kernel(int N)
{
    __shared__ int wsum[8];
    const int t = threadIdx.x, lane = t & 31, wd = t >> 5;
    const int i = blockIdx.x * 256 + t;
    const int v = (i < N) ? g_cnt[i] : 0;
    int x = v;
#pragma unroll
    for (int off = 1; off < 32; off <<= 1) {
        int y = __shfl_up_sync(0xffffffffu, x, off);
        if (lane >= off) x += y;
    }
    if (lane == 31) wsum[wd] = x;
    __syncthreads();
    if (t < 8) {
        int w = wsum[t];
        int xs = w;
#pragma unroll
        for (int off = 1; off < 8; off <<= 1) {
            int y = __shfl_up_sync(0x000000ffu, xs, off);
            if (t >= off) xs += y;
        }
        wsum[t] = xs - w;                       // exclusive warp offset
        if (t == 7) g_bsum[blockIdx.x] = xs;    // block total
    }
    __syncthreads();
    if (i < N) g_roff[i] = x - v + wsum[wd];
}

// ---------------------------------------------------------------------------
// Scan stage 2+3 merged: each block recomputes its block-prefix from g_bsum
// (block reduce over < nb ints — cheap, redundant, spin-free), then applies.
// ---------------------------------------------------------------------------
__global__ __launch_bounds__(256) void scan23_kernel(int N, int E, int nb)
{
    __shared__ int wred[8];
    const int t = threadIdx.x, lane = t & 31, wd = t >> 5;
    const int bid = blockIdx.x;

    int acc = 0;
    for (int j = t; j < bid; j += 256) acc += g_bsum[j];
#pragma unroll
    for (int off = 16; off > 0; off >>= 1)
        acc += __shfl_xor_sync(0xffffffffu, acc, off);
    if (lane == 0) wred[wd] = acc;
    __syncthreads();
    if (t == 0) {
        int s = 0;
#pragma unroll
        for (int j = 0; j < 8; j++) s += wred[j];
        wred[0] = s;
    }
    __syncthreads();
    const int boff = wred[0];

    const int i = bid * 256 + t;
    if (i < N) {
        const int r = g_roff[i] + boff;
        g_roff[i] = r;
        g_cur[i]  = r;
    }
    if (bid == 0 && t == 0) g_roff[N] = E;
}

// ---------------------------------------------------------------------------
// Scatter src ids into CSR order (int4 loads)
// ---------------------------------------------------------------------------
__global__ void scatter_kernel(const int* __restrict__ src,
                               const int* __restrict__ dst, int E)
{
    const int i4 = (blockIdx.x * blockDim.x + threadIdx.x) * 4;
    if (i4 + 3 < E) {
        const int4 d = *(const int4*)(dst + i4);
        const int4 s = *(const int4*)(src + i4);
        g_esrc[atomicAdd(&g_cur[d.x], 1)] = s.x;
        g_esrc[atomicAdd(&g_cur[d.y], 1)] = s.y;
        g_esrc[atomicAdd(&g_cur[d.z], 1)] = s.z;
        g_esrc[atomicAdd(&g_cur[d.w], 1)] = s.w;
    } else {
        for (int j = i4; j < E; j++)
            g_esrc[atomicAdd(&g_cur[dst[j]], 1)] = src[j];
    }
}

// ---------------------------------------------------------------------------
// Fused edge-softmax + aggregation. One warp per destination node, R11's
// lean consumption (lane l owns features 2l..2l+1; own head hh = l>>3; 3-xor
// dot reduce; 3 relative xor shuffles for other heads; z recovered after the
// loop) with a TWO-DEEP register software pipeline: edges p and p+1 resident,
// prefetch distance 2 -> up to 6 independent LDG.64s in flight per lane.
// ---------------------------------------------------------------------------
__global__ __launch_bounds__(256) void gather_kernel(
    const float* __restrict__ b,
    float* __restrict__ out,
    int N)
{
    const int n    = (blockIdx.x * 256 + threadIdx.x) >> 5;
    const int lane = threadIdx.x & 31;
    if (n >= N) return;
    const int hh = lane >> 3;   // own head

    const float2 q2 = ((const float2*)(g_q + (size_t)n * 64))[lane];
    const int p0 = g_roff[n];
    const int p1 = g_roff[n + 1];

    float2 a0 = make_float2(0.f, 0.f), a1 = a0, a2 = a0, a3 = a0;
    float z0 = 0.f;

#define GK_LOAD(kk, ww, sid)                                              \
    do {                                                                  \
        const float2* _kp = (const float2*)(g_kw + (size_t)(sid) * 128);  \
        kk = _kp[lane];                                                   \
        ww = _kp[lane + 32];                                              \
    } while (0)

#define GK_CONSUME(kk, ww)                                                \
    do {                                                                  \
        float prod = kk.x * q2.x + kk.y * q2.y;                           \
        prod += __shfl_xor_sync(0xffffffffu, prod, 4);                    \
        prod += __shfl_xor_sync(0xffffffffu, prod, 2);                    \
        prod += __shfl_xor_sync(0xffffffffu, prod, 1);                    \
        const float ew = __expf(prod);                                    \
        const float eA = __shfl_xor_sync(0xffffffffu, ew, 8);             \
        const float eB = __shfl_xor_sync(0xffffffffu, ew, 16);            \
        const float eC = __shfl_xor_sync(0xffffffffu, ew, 24);            \
        z0 += ew;                                                         \
        a0.x += ew * ww.x; a0.y += ew * ww.y;                             \
        a1.x += eA * ww.x; a1.y += eA * ww.y;                             \
        a2.x += eB * ww.x; a2.y += eB * ww.y;                             \
        a3.x += eC * ww.x; a3.y += eC * ww.y;                             \
    } while (0)

    if (p0 < p1) {
        float2 ka, wa, kb, wb;
        GK_LOAD(ka, wa, g_esrc[p0]);
        if (p0 + 1 < p1) GK_LOAD(kb, wb, g_esrc[p0 + 1]);

        int p = p0;
        for (; p + 1 < p1; p += 2) {
            float2 kn0 = ka, wn0 = wa, kn1 = kb, wn1 = wb;
            if (p + 2 < p1) GK_LOAD(kn0, wn0, g_esrc[p + 2]);
            if (p + 3 < p1) GK_LOAD(kn1, wn1, g_esrc[p + 3]);

            GK_CONSUME(ka, wa);
            GK_CONSUME(kb, wb);

            ka = kn0; wa = wn0; kb = kn1; wb = wn1;
        }
        if (p < p1) GK_CONSUME(ka, wa);
    }
#undef GK_LOAD
#undef GK_CONSUME

    // other heads' z from own-head lanes
    const float z1 = __shfl_xor_sync(0xffffffffu, z0, 8);
    const float z2 = __shfl_xor_sync(0xffffffffu, z0, 16);
    const float z3 = __shfl_xor_sync(0xffffffffu, z0, 24);

    const float i0 = (z0 > 0.f) ? 1.f / z0 : 0.f;
    const float i1 = (z1 > 0.f) ? 1.f / z1 : 0.f;
    const float i2 = (z2 > 0.f) ? 1.f / z2 : 0.f;
    const float i3 = (z3 > 0.f) ? 1.f / z3 : 0.f;

    const float2 bb = ((const float2*)b)[lane];   // features 2l, 2l+1
    float* op = out + (size_t)n * 256 + 2 * lane;

    *(float2*)(op + (size_t)(hh     ) * 64) = make_float2(a0.x * i0 + bb.x, a0.y * i0 + bb.y);
    *(float2*)(op + (size_t)(hh ^ 1) * 64) = make_float2(a1.x * i1 + bb.x, a1.y * i1 + bb.y);
    *(float2*)(op + (size_t)(hh ^ 2) * 64) = make_float2(a2.x * i2 + bb.x, a2.y * i2 + bb.y);
    *(float2*)(op + (size_t)(hh ^ 3) * 64) = make_float2(a3.x * i3 + bb.x, a3.y * i3 + bb.y);
}

// ---------------------------------------------------------------------------
extern "C" void kernel_launch(void* const* d_in, const int* in_sizes, int n_in,
                              void* d_out, int out_size)
{
    const float* h   = (const float*)d_in[0];
    const int*   src = (const int*)  d_in[1];
    const int*   dst = (const int*)  d_in[2];
    const float* Wk  = (const float*)d_in[3];
    const float* Wq  = (const float*)d_in[4];
    const float* Ww  = (const float*)d_in[5];
    const float* b   = (const float*)d_in[6];
    float*       out = (float*)d_out;

    const int N  = in_sizes[0] / 64;
    const int E  = in_sizes[1];
    const int nb = (N + 255) / 256;

    static void* cnt_ptr = nullptr;
    static cudaStream_t sideStream = nullptr;
    static cudaEvent_t  evFork = nullptr, evJoin = nullptr;
    if (cnt_ptr == nullptr) {
        cudaGetSymbolAddress(&cnt_ptr, g_cnt);
        cudaStreamCreateWithFlags(&sideStream, cudaStreamNonBlocking);
        cudaEventCreateWithFlags(&evFork, cudaEventDisableTiming);
        cudaEventCreateWithFlags(&evJoin, cudaEventDisableTiming);
    }

    // Fork: pure gemm (h,W only) overlaps the whole CSR chain (src,dst only).
    cudaEventRecord(evFork, 0);
    cudaStreamWaitEvent(sideStream, evFork, 0);
    gemm_mma_kernel<<<(N + 31) / 32, 192, 0, sideStream>>>(h, Wk, Wq, Ww, N);
    cudaEventRecord(evJoin, sideStream);

    cudaMemsetAsync(cnt_ptr, 0, (size_t)N * sizeof(int));
    hist_kernel<<<(E / 4 + 255) / 256, 256>>>(dst, E);
    scan1_kernel<<<nb, 256>>>(N);
    scan23_kernel<<<nb, 256>>>(N, E, nb);
    scatter_kernel<<<(E / 4 + 255) / 256, 256>>>(src, dst, E);

    cudaStreamWaitEvent(0, evJoin, 0);
    gather_kernel<<<(N + 7) / 8, 256>>>(b, out, N);
}